// round 9
// baseline (speedup 1.0000x reference)
#include <cuda_runtime.h>
#include <math.h>
#include <stdint.h>

#define Bdim   64
#define Sdim   2048
#define Cdim   128
#define CHUNK  64
#define KCH    (Sdim / CHUNK)     // 32
#define WARM   24                 // state err <= 0.465^24 ~ 1e-8
#define PRE    (WARM + 4)         // 28 rows ahead of t0 (incl 4 lag rows)
#define ROWS   (PRE + CHUNK)      // 92 rows resident in smem
#define NB     (Bdim * KCH)       // 2048 blocks
#define ROW    64                 // u64 (float2) elements per channel-row
#define MWARM  (WARM / 8)         // 3
#define MMAIN  (CHUNK / 8)        // 8

typedef unsigned long long u64;

__device__ float        g_partial[NB];
__device__ unsigned int g_count;          // zero-init; last block resets to 0

// ---- packed f32x2 helpers (sm_103a FFMA2 is PTX-only) ----
__device__ __forceinline__ u64 bcast2(float x) {
    u64 r; asm("mov.b64 %0, {%1, %1};" : "=l"(r) : "f"(x)); return r;
}
__device__ __forceinline__ void fma2(u64& d, u64 a, u64 b, u64 c) {
    asm("fma.rn.f32x2 %0, %1, %2, %3;" : "=l"(d) : "l"(a), "l"(b), "l"(c));
}
__device__ __forceinline__ float2 unpack2(u64 v) {
    float2 f; asm("mov.b64 {%0, %1}, %2;" : "=f"(f.x), "=f"(f.y) : "l"(v)); return f;
}
__device__ __forceinline__ uint32_t s2u(const void* p) {
    uint32_t a;
    asm("{ .reg .u64 t; cvta.to.shared.u64 t, %1; cvt.u32.u64 %0, t; }"
        : "=r"(a) : "l"(p));
    return a;
}
__device__ __forceinline__ void mbar_wait(uint32_t mbar, uint32_t parity) {
    asm volatile(
        "{\n\t.reg .pred P1;\n\t"
        "W_%=:\n\t"
        "mbarrier.try_wait.parity.acquire.cta.shared::cta.b64 P1, [%0], %1, 0x989680;\n\t"
        "@P1 bra.uni D_%=;\n\t"
        "bra.uni W_%=;\n\t"
        "D_%=:\n\t}"
        :: "r"(mbar), "r"(parity) : "memory");
}

struct St {
    u64 y1, y2, y3, y4;   // y lags
    u64 e1, e2, e3, e4;   // e lags
    u64 ss;               // packed sum of squares
};

template <bool ACC>
__device__ __forceinline__ void step8(u64 (&A)[8], St& s,
                                      u64 np0, u64 np1, u64 np2, u64 np3,
                                      u64 nq0, u64 nq1, u64 nq2, u64 nq3) {
#pragma unroll
    for (int j = 0; j < 8; j++) {
        u64 yt = A[j];
        u64 z = yt;
        fma2(z, np0, s.y1, z); fma2(z, np1, s.y2, z);
        fma2(z, np2, s.y3, z); fma2(z, np3, s.y4, z);
        fma2(z, nq3, s.e4, z); fma2(z, nq2, s.e3, z); fma2(z, nq1, s.e2, z);
        u64 e; fma2(e, nq0, s.e1, z);
        if (ACC) fma2(s.ss, e, e, s.ss);
        s.y4 = s.y3; s.y3 = s.y2; s.y2 = s.y1; s.y1 = yt;
        s.e4 = s.e3; s.e3 = s.e2; s.e2 = s.e1; s.e1 = e;
    }
}

// ============================================================
// Bulk-async version: one cp.async.bulk pulls the whole time tile
// (92 rows x 512B = 46KB) into SMEM; warps compute from SMEM (LDS.64).
// Global latency is paid ONCE per block via mbarrier, not per load.
//   grid = B*KCH blocks of 64 threads; thread owns 2 channels (f32x2).
// ============================================================
__global__ void __launch_bounds__(64)
arima_fused(const float* __restrict__ y,
            const float* __restrict__ phi,
            const float* __restrict__ theta,
            const float* __restrict__ sigma2,
            float* __restrict__ out) {
    __shared__ __align__(16) u64 tile[ROWS * ROW];   // 47104 B
    __shared__ __align__(8)  u64 mbar;
    __shared__ float red[64];
    __shared__ int isLast;

    const int bid = blockIdx.x;
    const int b   = bid >> 5;            // KCH == 32
    const int ch  = bid & (KCH - 1);
    const int tid = threadIdx.x;

    const uint32_t mb = s2u(&mbar);

    // ---- issue the bulk copy ASAP (before coefficient loads) ----
    if (tid == 0) {
        asm volatile("mbarrier.init.shared.b64 [%0], 1;" :: "r"(mb) : "memory");
    }
    __syncthreads();
    if (tid == 0) {
        const u64* src;
        uint32_t dst;
        uint32_t bytes;
        if (ch != 0) {   // rows 0..91 = times t0-PRE .. t0+CHUNK-1
            src   = ((const u64*)y) + ((size_t)b * Sdim + ch * CHUNK - PRE) * ROW;
            dst   = s2u(tile);
            bytes = ROWS * ROW * 8;                       // 47104
        } else {         // rows PRE..91 = times 0..CHUNK-1
            src   = ((const u64*)y) + ((size_t)b * Sdim) * ROW;
            dst   = s2u(tile + PRE * ROW);
            bytes = CHUNK * ROW * 8;                      // 32768
        }
        asm volatile("mbarrier.arrive.expect_tx.shared.b64 _, [%0], %1;"
                     :: "r"(mb), "r"(bytes) : "memory");
        asm volatile("cp.async.bulk.shared::cta.global.mbarrier::complete_tx::bytes "
                     "[%0], [%1], %2, [%3];"
                     :: "r"(dst), "l"(src), "r"(bytes), "r"(mb) : "memory");
    }

    // coefficients overlap with the bulk copy
    const u64 np0 = bcast2(-phi[0]),   np1 = bcast2(-phi[1]);
    const u64 np2 = bcast2(-phi[2]),   np3 = bcast2(-phi[3]);
    const u64 nq0 = bcast2(-theta[0]), nq1 = bcast2(-theta[1]);
    const u64 nq2 = bcast2(-theta[2]), nq3 = bcast2(-theta[3]);

    St s;
    s.e1 = s.e2 = s.e3 = s.e4 = 0ull;
    s.ss = 0ull;

    if (ch == 0) {
        // thread-local zero lags (each thread reads only its own column)
        tile[(PRE - 1) * ROW + tid] = 0ull;
        tile[(PRE - 2) * ROW + tid] = 0ull;
        tile[(PRE - 3) * ROW + tid] = 0ull;
        tile[(PRE - 4) * ROW + tid] = 0ull;
    }

    mbar_wait(mb, 0);

    const u64* T = tile + tid;           // column base; rows stride ROW
    u64 A[8], Bf[8];

    if (ch != 0) {
        s.y1 = T[(PRE - WARM - 1) * ROW]; s.y2 = T[(PRE - WARM - 2) * ROW];
        s.y3 = T[(PRE - WARM - 3) * ROW]; s.y4 = T[(PRE - WARM - 4) * ROW];
        int r = PRE - WARM;              // == 4
#pragma unroll
        for (int i = 0; i < 8; i++) A[i] = T[(size_t)(r + i) * ROW];
        r += 8;
        // warm: 3 macro-tiles (no ss), main: 8 macro-tiles
#pragma unroll
        for (int m = 0; m < MWARM + MMAIN; m++) {
            if (m + 1 < MWARM + MMAIN) {
#pragma unroll
                for (int i = 0; i < 8; i++) Bf[i] = T[(size_t)(r + i) * ROW];
                r += 8;
            }
            if (m < MWARM) step8<false>(A, s, np0, np1, np2, np3, nq0, nq1, nq2, nq3);
            else           step8<true >(A, s, np0, np1, np2, np3, nq0, nq1, nq2, nq3);
#pragma unroll
            for (int i = 0; i < 8; i++) A[i] = Bf[i];
        }
    } else {
        s.y1 = T[(PRE - 1) * ROW]; s.y2 = T[(PRE - 2) * ROW];
        s.y3 = T[(PRE - 3) * ROW]; s.y4 = T[(PRE - 4) * ROW];
        int r = PRE;
#pragma unroll
        for (int i = 0; i < 8; i++) A[i] = T[(size_t)(r + i) * ROW];
        r += 8;
#pragma unroll
        for (int m = 0; m < MMAIN; m++) {
            if (m + 1 < MMAIN) {
#pragma unroll
                for (int i = 0; i < 8; i++) Bf[i] = T[(size_t)(r + i) * ROW];
                r += 8;
            }
            step8<true>(A, s, np0, np1, np2, np3, nq0, nq1, nq2, nq3);
#pragma unroll
            for (int i = 0; i < 8; i++) A[i] = Bf[i];
        }
    }

    // ---- block reduction ----
    float2 sv = unpack2(s.ss);
    red[tid] = sv.x + sv.y;
    __syncthreads();
#pragma unroll
    for (int o = 32; o > 0; o >>= 1) {
        if (tid < o) red[tid] += red[tid + o];
        __syncthreads();
    }

    // ---- last-block-done final reduce + NLL ----
    if (tid == 0) {
        g_partial[bid] = red[0];
        __threadfence();
        unsigned int c = atomicAdd(&g_count, 1u);
        isLast = (c == (unsigned int)(NB - 1));
    }
    __syncthreads();
    if (isLast) {
        __threadfence();                      // acquire side of the handoff
        float acc = 0.f;
#pragma unroll
        for (int i = 0; i < NB / 64; i++)     // fixed order -> deterministic
            acc += g_partial[tid + 64 * i];
        red[tid] = acc;
        __syncthreads();
#pragma unroll
        for (int o = 32; o > 0; o >>= 1) {
            if (tid < o) red[tid] += red[tid + o];
            __syncthreads();
        }
        if (tid == 0) {
            float s2 = sigma2[0];
            out[0] = 0.5f * (float)Sdim * logf(6.283185307179586f * s2)
                   + 0.5f * red[0] / s2;
            g_count = 0u;                     // restore invariant for next replay
        }
    }
}

extern "C" void kernel_launch(void* const* d_in, const int* in_sizes, int n_in,
                              void* d_out, int out_size) {
    const float* y      = (const float*)d_in[0];
    const float* phi    = (const float*)d_in[1];
    const float* theta  = (const float*)d_in[2];
    const float* sigma2 = (const float*)d_in[3];
    float* out = (float*)d_out;
    (void)in_sizes; (void)n_in; (void)out_size;

    arima_fused<<<NB, 64>>>(y, phi, theta, sigma2, out);
}

// round 12
// speedup vs baseline: 1.0621x; 1.0621x over previous
#include <cuda_runtime.h>
#include <math.h>

#define Bdim   64
#define Sdim   2048
#define Cdim   128
#define CHUNK  64
#define KCH    (Sdim / CHUNK)     // 32 chunks
#define NPAIR  (KCH / 2)          // 16 chunk-pairs per batch row
#define WARM   16                 // state err <= 0.465^16 ~ 5e-6 (measured 0.0)
#define NB     (Bdim * NPAIR)     // 1024 blocks
#define ROW    64                 // u64 (float2) elements per channel-row
#define MWARM  (WARM / 8)         // 2
#define MMAIN  (CHUNK / 8)        // 8
#define MTOT   (MWARM + MMAIN)    // 10

typedef unsigned long long u64;

__device__ float        g_partial[NB];
__device__ unsigned int g_count;          // zero-init; last block resets to 0

// ---- packed f32x2 helpers (sm_103a FFMA2 is PTX-only) ----
__device__ __forceinline__ u64 bcast2(float x) {
    u64 r; asm("mov.b64 %0, {%1, %1};" : "=l"(r) : "f"(x)); return r;
}
__device__ __forceinline__ void fma2(u64& d, u64 a, u64 b, u64 c) {
    asm("fma.rn.f32x2 %0, %1, %2, %3;" : "=l"(d) : "l"(a), "l"(b), "l"(c));
}
__device__ __forceinline__ float2 unpack2(u64 v) {
    float2 f; asm("mov.b64 {%0, %1}, %2;" : "=f"(f.x), "=f"(f.y) : "l"(v)); return f;
}

struct St {
    u64 y1, y2, y3, y4;   // y lags
    u64 e1, e2, e3, e4;   // e lags
    u64 ss;               // packed sum of squares
};

// one 8-step register tile; ACC selects ss accumulation (compile-time)
template <bool ACC>
__device__ __forceinline__ void step8(u64 (&A)[8], St& s,
                                      u64 np0, u64 np1, u64 np2, u64 np3,
                                      u64 nq0, u64 nq1, u64 nq2, u64 nq3) {
#pragma unroll
    for (int j = 0; j < 8; j++) {
        u64 yt = A[j];
        u64 z = yt;
        fma2(z, np0, s.y1, z); fma2(z, np1, s.y2, z);
        fma2(z, np2, s.y3, z); fma2(z, np3, s.y4, z);
        fma2(z, nq3, s.e4, z); fma2(z, nq2, s.e3, z); fma2(z, nq1, s.e2, z);
        u64 e; fma2(e, nq0, s.e1, z);
        if (ACC) fma2(s.ss, e, e, s.ss);
        s.y4 = s.y3; s.y3 = s.y2; s.y2 = s.y1; s.y1 = yt;
        s.e4 = s.e3; s.e3 = s.e2; s.e2 = s.e1; s.e1 = e;
    }
}

__device__ __forceinline__ void load8(u64 (&T)[8], const u64* P) {
#pragma unroll
    for (int i = 0; i < 8; i++) T[i] = P[(size_t)i * ROW];
}
__device__ __forceinline__ void copy8(u64 (&D)[8], const u64 (&S)[8]) {
#pragma unroll
    for (int i = 0; i < 8; i++) D[i] = S[i];
}
__device__ __forceinline__ void lags(St& s, const u64* P) {
    s.y1 = P[-1 * (int)ROW]; s.y2 = P[-2 * (int)ROW];
    s.y3 = P[-3 * (int)ROW]; s.y4 = P[-4 * (int)ROW];
}

// ============================================================
// DUAL-CHAIN kernel: each thread runs TWO independent chunk recurrences
// (chunks 2j and 2j+1 of the same batch row), interleaved in one
// instruction stream -> 2x per-warp ILP and 2x outstanding loads.
//   grid = B*NPAIR blocks of 64 threads; thread owns 2 channels (f32x2).
// ============================================================
__global__ void __launch_bounds__(64)
arima_fused(const float* __restrict__ y,
            const float* __restrict__ phi,
            const float* __restrict__ theta,
            const float* __restrict__ sigma2,
            float* __restrict__ out) {
    const int bid = blockIdx.x;
    const int b   = bid >> 4;            // NPAIR == 16
    const int jp  = bid & (NPAIR - 1);
    const int tid = threadIdx.x;

    const u64 np0 = bcast2(-phi[0]),   np1 = bcast2(-phi[1]);
    const u64 np2 = bcast2(-phi[2]),   np3 = bcast2(-phi[3]);
    const u64 nq0 = bcast2(-theta[0]), nq1 = bcast2(-theta[1]);
    const u64 nq2 = bcast2(-theta[2]), nq3 = bcast2(-theta[3]);

    St sa, sb;
    sa.e1 = sa.e2 = sa.e3 = sa.e4 = 0ull; sa.ss = 0ull;
    sb.e1 = sb.e2 = sb.e3 = sb.e4 = 0ull; sb.ss = 0ull;

    const u64* base = ((const u64*)y) + (size_t)b * Sdim * ROW + tid;
    u64 Aa[8], Ab[8], Ba[8], Bb[8];

    if (jp != 0) {
        // both chains warm (chunks 2jp, 2jp+1)
        const u64* Pa = base + (size_t)(2 * jp * CHUNK - WARM) * ROW;
        const u64* Pb = base + (size_t)((2 * jp + 1) * CHUNK - WARM) * ROW;
        lags(sa, Pa); lags(sb, Pb);
        load8(Aa, Pa); Pa += 8 * ROW;
        load8(Ab, Pb); Pb += 8 * ROW;
#pragma unroll
        for (int m = 0; m < MTOT; m++) {
            if (m + 1 < MTOT) {
                load8(Ba, Pa); Pa += 8 * ROW;
                load8(Bb, Pb); Pb += 8 * ROW;
            }
            if (m < MWARM) {
                step8<false>(Aa, sa, np0, np1, np2, np3, nq0, nq1, nq2, nq3);
                step8<false>(Ab, sb, np0, np1, np2, np3, nq0, nq1, nq2, nq3);
            } else {
                step8<true>(Aa, sa, np0, np1, np2, np3, nq0, nq1, nq2, nq3);
                step8<true>(Ab, sb, np0, np1, np2, np3, nq0, nq1, nq2, nq3);
            }
            if (m + 1 < MTOT) { copy8(Aa, Ba); copy8(Ab, Bb); }
        }
    } else {
        // chain a = chunk 0 (no warm, exact zero lags), chain b = chunk 1 (warm)
        const u64* Pa = base;
        const u64* Pb = base + (size_t)(CHUNK - WARM) * ROW;
        sa.y1 = sa.y2 = sa.y3 = sa.y4 = 0ull;
        lags(sb, Pb);
        // b's warm tiles first (chain a's loads overlap via prologue load)
        load8(Ab, Pb); Pb += 8 * ROW;
#pragma unroll
        for (int m = 0; m < MWARM; m++) {
            load8(Bb, Pb); Pb += 8 * ROW;
            step8<false>(Ab, sb, np0, np1, np2, np3, nq0, nq1, nq2, nq3);
            copy8(Ab, Bb);
        }
        load8(Aa, Pa); Pa += 8 * ROW;
#pragma unroll
        for (int m = 0; m < MMAIN; m++) {
            if (m + 1 < MMAIN) {
                load8(Ba, Pa); Pa += 8 * ROW;
                load8(Bb, Pb); Pb += 8 * ROW;
            }
            step8<true>(Aa, sa, np0, np1, np2, np3, nq0, nq1, nq2, nq3);
            step8<true>(Ab, sb, np0, np1, np2, np3, nq0, nq1, nq2, nq3);
            if (m + 1 < MMAIN) { copy8(Aa, Ba); copy8(Ab, Bb); }
        }
    }

    // ---- block reduction ----
    float2 va = unpack2(sa.ss);
    float2 vb = unpack2(sb.ss);
    __shared__ float red[64];
    red[tid] = (va.x + va.y) + (vb.x + vb.y);
    __syncthreads();
#pragma unroll
    for (int o = 32; o > 0; o >>= 1) {
        if (tid < o) red[tid] += red[tid + o];
        __syncthreads();
    }

    // ---- last-block-done final reduce + NLL ----
    __shared__ int isLast;
    if (tid == 0) {
        g_partial[bid] = red[0];
        __threadfence();
        unsigned int c = atomicAdd(&g_count, 1u);
        isLast = (c == (unsigned int)(NB - 1));
    }
    __syncthreads();
    if (isLast) {
        __threadfence();                      // acquire side of the handoff
        float acc = 0.f;
#pragma unroll
        for (int i = 0; i < NB / 64; i++)     // fixed order -> deterministic
            acc += g_partial[tid + 64 * i];
        red[tid] = acc;
        __syncthreads();
#pragma unroll
        for (int o = 32; o > 0; o >>= 1) {
            if (tid < o) red[tid] += red[tid + o];
            __syncthreads();
        }
        if (tid == 0) {
            float s2 = sigma2[0];
            out[0] = 0.5f * (float)Sdim * logf(6.283185307179586f * s2)
                   + 0.5f * red[0] / s2;
            g_count = 0u;                     // restore invariant for next replay
        }
    }
}

extern "C" void kernel_launch(void* const* d_in, const int* in_sizes, int n_in,
                              void* d_out, int out_size) {
    const float* y      = (const float*)d_in[0];
    const float* phi    = (const float*)d_in[1];
    const float* theta  = (const float*)d_in[2];
    const float* sigma2 = (const float*)d_in[3];
    float* out = (float*)d_out;
    (void)in_sizes; (void)n_in; (void)out_size;

    arima_fused<<<NB, 64>>>(y, phi, theta, sigma2, out);
}

// round 14
// speedup vs baseline: 1.1589x; 1.0911x over previous
#include <cuda_runtime.h>
#include <math.h>

#define Bdim   64
#define Sdim   2048
#define Cdim   128
#define CHUNK  64
#define KCH    (Sdim / CHUNK)     // 32
#define WARM   16                 // state err <= 0.465^16 ~ 5e-6 (measured 1.2e-7)
#define NB     (Bdim * KCH)       // 2048 blocks
#define ROW    64                 // u64 (float2) elements per channel-row
#define MWARM  (WARM / 8)         // 2
#define MMAIN  (CHUNK / 8)        // 8
#define MTOT   (MWARM + MMAIN)    // 10

typedef unsigned long long u64;

__device__ float        g_partial[NB];
__device__ unsigned int g_count;          // zero-init; last block resets to 0

// ---- packed f32x2 helpers (sm_103a FFMA2 is PTX-only) ----
__device__ __forceinline__ u64 bcast2(float x) {
    u64 r; asm("mov.b64 %0, {%1, %1};" : "=l"(r) : "f"(x)); return r;
}
__device__ __forceinline__ void fma2(u64& d, u64 a, u64 b, u64 c) {
    asm("fma.rn.f32x2 %0, %1, %2, %3;" : "=l"(d) : "l"(a), "l"(b), "l"(c));
}
__device__ __forceinline__ float2 unpack2(u64 v) {
    float2 f; asm("mov.b64 {%0, %1}, %2;" : "=f"(f.x), "=f"(f.y) : "l"(v)); return f;
}
// volatile LDG: ptxas cannot sink/reschedule it -> the 8-wide batch SURVIVES
__device__ __forceinline__ u64 ldg64v(const u64* p) {
    u64 r; asm volatile("ld.global.nc.b64 %0, [%1];" : "=l"(r) : "l"(p));
    return r;
}

struct St {
    u64 y1, y2, y3, y4;   // y lags
    u64 e1, e2, e3, e4;   // e lags
    u64 ss;               // packed sum of squares
};

// one 8-step register tile; ACC selects ss accumulation (compile-time)
template <bool ACC>
__device__ __forceinline__ void step8(u64 (&A)[8], St& s,
                                      u64 np0, u64 np1, u64 np2, u64 np3,
                                      u64 nq0, u64 nq1, u64 nq2, u64 nq3) {
#pragma unroll
    for (int j = 0; j < 8; j++) {
        u64 yt = A[j];
        u64 z = yt;
        fma2(z, np0, s.y1, z); fma2(z, np1, s.y2, z);
        fma2(z, np2, s.y3, z); fma2(z, np3, s.y4, z);
        fma2(z, nq3, s.e4, z); fma2(z, nq2, s.e3, z); fma2(z, nq1, s.e2, z);
        u64 e; fma2(e, nq0, s.e1, z);
        if (ACC) fma2(s.ss, e, e, s.ss);
        s.y4 = s.y3; s.y3 = s.y2; s.y2 = s.y1; s.y1 = yt;
        s.e4 = s.e3; s.e3 = s.e2; s.e2 = s.e1; s.e1 = e;
    }
}

__device__ __forceinline__ void load8v(u64 (&T)[8], const u64* P) {
#pragma unroll
    for (int i = 0; i < 8; i++) T[i] = ldg64v(P + (size_t)i * ROW);
}
__device__ __forceinline__ void copy8(u64 (&D)[8], const u64 (&S)[8]) {
#pragma unroll
    for (int i = 0; i < 8; i++) D[i] = S[i];
}

// ============================================================
// R5 geometry (the measured optimum: 2048 blocks x 64 threads, one chain
// per thread) + asm-volatile pinned 8-deep LDG batches + WARM=16.
//   Warm-up WARM steps with zero MA state, then sum(e^2) over CHUNK steps.
//   Last finishing block reduces the partials and writes the NLL.
// ============================================================
__global__ void __launch_bounds__(64)
arima_fused(const float* __restrict__ y,
            const float* __restrict__ phi,
            const float* __restrict__ theta,
            const float* __restrict__ sigma2,
            float* __restrict__ out) {
    const int bid = blockIdx.x;
    const int b   = bid >> 5;            // KCH == 32
    const int ch  = bid & (KCH - 1);
    const int tid = threadIdx.x;

    const u64 np0 = bcast2(-phi[0]),   np1 = bcast2(-phi[1]);
    const u64 np2 = bcast2(-phi[2]),   np3 = bcast2(-phi[3]);
    const u64 nq0 = bcast2(-theta[0]), nq1 = bcast2(-theta[1]);
    const u64 nq2 = bcast2(-theta[2]), nq3 = bcast2(-theta[3]);

    St s;
    s.e1 = s.e2 = s.e3 = s.e4 = 0ull;
    s.ss = 0ull;

    u64 A[8], Bf[8];

    if (ch != 0) {
        const u64* P = ((const u64*)y)
                     + ((size_t)b * Sdim + ch * CHUNK - WARM) * ROW + tid;
        // pinned batch: 4 lags + first tile issued together (12 in flight)
        s.y1 = ldg64v(P - 1 * (int)ROW); s.y2 = ldg64v(P - 2 * (int)ROW);
        s.y3 = ldg64v(P - 3 * (int)ROW); s.y4 = ldg64v(P - 4 * (int)ROW);
        load8v(A, P); P += 8 * ROW;
        // 10 tiles: 2 warm (no ss) + 8 main; prefetch next while stepping
#pragma unroll
        for (int m = 0; m < MTOT; m++) {
            if (m + 1 < MTOT) { load8v(Bf, P); P += 8 * ROW; }
            if (m < MWARM) step8<false>(A, s, np0, np1, np2, np3, nq0, nq1, nq2, nq3);
            else           step8<true >(A, s, np0, np1, np2, np3, nq0, nq1, nq2, nq3);
            if (m + 1 < MTOT) copy8(A, Bf);
        }
    } else {
        const u64* P = ((const u64*)y) + ((size_t)b * Sdim) * ROW + tid;
        s.y1 = s.y2 = s.y3 = s.y4 = 0ull;        // series start: exact zeros
        load8v(A, P); P += 8 * ROW;
#pragma unroll
        for (int m = 0; m < MMAIN; m++) {
            if (m + 1 < MMAIN) { load8v(Bf, P); P += 8 * ROW; }
            step8<true>(A, s, np0, np1, np2, np3, nq0, nq1, nq2, nq3);
            if (m + 1 < MMAIN) copy8(A, Bf);
        }
    }

    // ---- block reduction ----
    float2 sv = unpack2(s.ss);
    __shared__ float red[64];
    red[tid] = sv.x + sv.y;
    __syncthreads();
#pragma unroll
    for (int o = 32; o > 0; o >>= 1) {
        if (tid < o) red[tid] += red[tid + o];
        __syncthreads();
    }

    // ---- last-block-done final reduce + NLL ----
    __shared__ int isLast;
    if (tid == 0) {
        g_partial[bid] = red[0];
        __threadfence();
        unsigned int c = atomicAdd(&g_count, 1u);
        isLast = (c == (unsigned int)(NB - 1));
    }
    __syncthreads();
    if (isLast) {
        __threadfence();                      // acquire side of the handoff
        float acc = 0.f;
#pragma unroll
        for (int i = 0; i < NB / 64; i++)     // fixed order -> deterministic
            acc += g_partial[tid + 64 * i];
        red[tid] = acc;
        __syncthreads();
#pragma unroll
        for (int o = 32; o > 0; o >>= 1) {
            if (tid < o) red[tid] += red[tid + o];
            __syncthreads();
        }
        if (tid == 0) {
            float s2 = sigma2[0];
            out[0] = 0.5f * (float)Sdim * logf(6.283185307179586f * s2)
                   + 0.5f * red[0] / s2;
            g_count = 0u;                     // restore invariant for next replay
        }
    }
}

extern "C" void kernel_launch(void* const* d_in, const int* in_sizes, int n_in,
                              void* d_out, int out_size) {
    const float* y      = (const float*)d_in[0];
    const float* phi    = (const float*)d_in[1];
    const float* theta  = (const float*)d_in[2];
    const float* sigma2 = (const float*)d_in[3];
    float* out = (float*)d_out;
    (void)in_sizes; (void)n_in; (void)out_size;

    arima_fused<<<NB, 64>>>(y, phi, theta, sigma2, out);
}

// round 17
// speedup vs baseline: 1.1789x; 1.0172x over previous
#include <cuda_runtime.h>
#include <math.h>

#define Bdim   64
#define Sdim   2048
#define Cdim   128
#define CHUNK  64
#define KCH    (Sdim / CHUNK)     // 32
#define WARM   16                 // state err <= 0.465^16 ~ 5e-6 (measured ~0)
#define NCHUNK (Bdim * KCH)       // 2048 chunks, one per WARP
#define NB     (NCHUNK / 2)       // 1024 blocks of 2 warps
#define ROW4   32                 // float4 elements per channel-row (128 ch)
#define MWARM  (WARM / 8)         // 2
#define MMAIN  (CHUNK / 8)        // 8
#define MTOT   (MWARM + MMAIN)    // 10

typedef unsigned long long u64;

__device__ float        g_partial[NB];
__device__ unsigned int g_count;          // zero-init; last block resets to 0

// ---- packed f32x2 helpers (sm_103a FFMA2 is PTX-only) ----
__device__ __forceinline__ u64 bcast2(float x) {
    u64 r; asm("mov.b64 %0, {%1, %1};" : "=l"(r) : "f"(x)); return r;
}
__device__ __forceinline__ void fma2(u64& d, u64 a, u64 b, u64 c) {
    asm("fma.rn.f32x2 %0, %1, %2, %3;" : "=l"(d) : "l"(a), "l"(b), "l"(c));
}
__device__ __forceinline__ float2 unpack2(u64 v) {
    float2 f; asm("mov.b64 {%0, %1}, %2;" : "=f"(f.x), "=f"(f.y) : "l"(v)); return f;
}
// pinned 16B vector load (LDG.E.128) -> two packed f32x2 lanes
__device__ __forceinline__ void ld128v(const float4* p, u64& a, u64& b) {
    asm volatile("ld.global.nc.v2.b64 {%0, %1}, [%2];"
                 : "=l"(a), "=l"(b) : "l"(p));
}

// dual-lane state: lane a = channels {4l,4l+1}, lane b = {4l+2,4l+3}
struct St {
    u64 y1a, y2a, y3a, y4a, y1b, y2b, y3b, y4b;
    u64 e1a, e2a, e3a, e4a, e1b, e2b, e3b, e4b;
    u64 ssa, ssb;
};

// one 8-step tile for 4 channels: two independent FMA2 chains interleaved
template <bool ACC>
__device__ __forceinline__ void step8(u64 (&Aa)[8], u64 (&Ab)[8], St& s,
                                      u64 np0, u64 np1, u64 np2, u64 np3,
                                      u64 nq0, u64 nq1, u64 nq2, u64 nq3) {
#pragma unroll
    for (int j = 0; j < 8; j++) {
        u64 ya = Aa[j], yb = Ab[j];
        u64 za = ya,    zb = yb;
        fma2(za, np0, s.y1a, za);  fma2(zb, np0, s.y1b, zb);
        fma2(za, np1, s.y2a, za);  fma2(zb, np1, s.y2b, zb);
        fma2(za, np2, s.y3a, za);  fma2(zb, np2, s.y3b, zb);
        fma2(za, np3, s.y4a, za);  fma2(zb, np3, s.y4b, zb);
        fma2(za, nq3, s.e4a, za);  fma2(zb, nq3, s.e4b, zb);
        fma2(za, nq2, s.e3a, za);  fma2(zb, nq2, s.e3b, zb);
        fma2(za, nq1, s.e2a, za);  fma2(zb, nq1, s.e2b, zb);
        u64 ea; fma2(ea, nq0, s.e1a, za);
        u64 eb; fma2(eb, nq0, s.e1b, zb);
        if (ACC) { fma2(s.ssa, ea, ea, s.ssa); fma2(s.ssb, eb, eb, s.ssb); }
        s.y4a = s.y3a; s.y3a = s.y2a; s.y2a = s.y1a; s.y1a = ya;
        s.y4b = s.y3b; s.y3b = s.y2b; s.y2b = s.y1b; s.y1b = yb;
        s.e4a = s.e3a; s.e3a = s.e2a; s.e2a = s.e1a; s.e1a = ea;
        s.e4b = s.e3b; s.e3b = s.e2b; s.e2b = s.e1b; s.e1b = eb;
    }
}

__device__ __forceinline__ void load8(u64 (&Ta)[8], u64 (&Tb)[8], const float4* P) {
#pragma unroll
    for (int i = 0; i < 8; i++) ld128v(P + (size_t)i * ROW4, Ta[i], Tb[i]);
}
__device__ __forceinline__ void copy8(u64 (&Da)[8], u64 (&Db)[8],
                                      const u64 (&Sa)[8], const u64 (&Sb)[8]) {
#pragma unroll
    for (int i = 0; i < 8; i++) { Da[i] = Sa[i]; Db[i] = Sb[i]; }
}

// ============================================================
// CHANNEL-SPLIT kernel: one WARP per chunk, 4 channels per thread via
// LDG.128 -> two independent packed-f32x2 recurrence chains per thread.
// Same single load stream as R5 but 2x arithmetic per load batch.
//   grid = 1024 blocks x 64 threads (2 warps = 2 chunks per block).
// ============================================================
__global__ void __launch_bounds__(64)
arima_fused(const float* __restrict__ y,
            const float* __restrict__ phi,
            const float* __restrict__ theta,
            const float* __restrict__ sigma2,
            float* __restrict__ out) {
    const int tid  = threadIdx.x;
    const int wid  = tid >> 5;
    const int lane = tid & 31;
    const int ci   = blockIdx.x * 2 + wid;   // global chunk id
    const int b    = ci >> 5;                // KCH == 32
    const int ch   = ci & (KCH - 1);

    const u64 np0 = bcast2(-phi[0]),   np1 = bcast2(-phi[1]);
    const u64 np2 = bcast2(-phi[2]),   np3 = bcast2(-phi[3]);
    const u64 nq0 = bcast2(-theta[0]), nq1 = bcast2(-theta[1]);
    const u64 nq2 = bcast2(-theta[2]), nq3 = bcast2(-theta[3]);

    St s;
    s.e1a = s.e2a = s.e3a = s.e4a = 0ull;
    s.e1b = s.e2b = s.e3b = s.e4b = 0ull;
    s.ssa = s.ssb = 0ull;

    u64 Aa[8], Ab[8], Ba[8], Bb[8];

    if (ch != 0) {
        const float4* P = (const float4*)y
                        + ((size_t)b * Sdim + ch * CHUNK - WARM) * ROW4 + lane;
        ld128v(P - 1 * ROW4, s.y1a, s.y1b);
        ld128v(P - 2 * ROW4, s.y2a, s.y2b);
        ld128v(P - 3 * ROW4, s.y3a, s.y3b);
        ld128v(P - 4 * ROW4, s.y4a, s.y4b);
        load8(Aa, Ab, P); P += 8 * ROW4;
#pragma unroll
        for (int m = 0; m < MTOT; m++) {
            if (m + 1 < MTOT) { load8(Ba, Bb, P); P += 8 * ROW4; }
            if (m < MWARM) step8<false>(Aa, Ab, s, np0, np1, np2, np3, nq0, nq1, nq2, nq3);
            else           step8<true >(Aa, Ab, s, np0, np1, np2, np3, nq0, nq1, nq2, nq3);
            if (m + 1 < MTOT) copy8(Aa, Ab, Ba, Bb);
        }
    } else {
        const float4* P = (const float4*)y + ((size_t)b * Sdim) * ROW4 + lane;
        s.y1a = s.y2a = s.y3a = s.y4a = 0ull;    // series start: exact zeros
        s.y1b = s.y2b = s.y3b = s.y4b = 0ull;
        load8(Aa, Ab, P); P += 8 * ROW4;
#pragma unroll
        for (int m = 0; m < MMAIN; m++) {
            if (m + 1 < MMAIN) { load8(Ba, Bb, P); P += 8 * ROW4; }
            step8<true>(Aa, Ab, s, np0, np1, np2, np3, nq0, nq1, nq2, nq3);
            if (m + 1 < MMAIN) copy8(Aa, Ab, Ba, Bb);
        }
    }

    // ---- warp reduction (shfl), then 2-warp block combine ----
    float2 fa = unpack2(s.ssa);
    float2 fb = unpack2(s.ssb);
    float v = (fa.x + fa.y) + (fb.x + fb.y);
#pragma unroll
    for (int o = 16; o > 0; o >>= 1)
        v += __shfl_down_sync(0xffffffffu, v, o);

    __shared__ float wsum[2];
    __shared__ int isLast;
    if (lane == 0) wsum[wid] = v;
    __syncthreads();

    // ---- last-block-done final reduce + NLL ----
    if (tid == 0) {
        g_partial[blockIdx.x] = wsum[0] + wsum[1];
        __threadfence();
        unsigned int c = atomicAdd(&g_count, 1u);
        isLast = (c == (unsigned int)(NB - 1));
    }
    __syncthreads();
    if (isLast) {
        __threadfence();                      // acquire side of the handoff
        float acc = 0.f;
#pragma unroll
        for (int i = 0; i < NB / 64; i++)     // fixed order -> deterministic
            acc += g_partial[tid + 64 * i];
        __shared__ float red[64];
        red[tid] = acc;
        __syncthreads();
#pragma unroll
        for (int o = 32; o > 0; o >>= 1) {
            if (tid < o) red[tid] += red[tid + o];
            __syncthreads();
        }
        if (tid == 0) {
            float s2 = sigma2[0];
            out[0] = 0.5f * (float)Sdim * logf(6.283185307179586f * s2)
                   + 0.5f * red[0] / s2;
            g_count = 0u;                     // restore invariant for next replay
        }
    }
}

extern "C" void kernel_launch(void* const* d_in, const int* in_sizes, int n_in,
                              void* d_out, int out_size) {
    const float* y      = (const float*)d_in[0];
    const float* phi    = (const float*)d_in[1];
    const float* theta  = (const float*)d_in[2];
    const float* sigma2 = (const float*)d_in[3];
    float* out = (float*)d_out;
    (void)in_sizes; (void)n_in; (void)out_size;

    arima_fused<<<NB, 64>>>(y, phi, theta, sigma2, out);
}